// round 10
// baseline (speedup 1.0000x reference)
#include <cuda_runtime.h>
#include <cuda_fp16.h>

// 5x5 masked median filter, 3x1024x1024 fp32, f16x2-packed, 4 pixels/thread
// (two independent half2 median chains per thread for ILP).
// Reference semantics: tap (y+dy, x+dx) valid iff 0<=y+dy<=H-2 && 0<=x+dx<=W-2.
// Output = mean of the two middle order statistics of valid taps.
// Interior: exact doubly-sorted-matrix selection in half2.
// Boundary (~1%): exact fp32 inf-masked partial selection sort.

#define MN2 __hmin2
#define MX2 __hmax2
#define CE2(a,b) { half2 _t2 = MN2(a,b); (b) = MX2(a,b); (a) = _t2; }
#define MNf fminf
#define MXf fmaxf
#define CEf(a,b) { float _tf = MNf(a,b); (b) = MXf(a,b); (a) = _tf; }

constexpr int H   = 1024;
constexpr int W   = 1024;
constexpr int C   = 3;
constexpr int TXP = 128;          // output pixels per block in x (32 lanes x 4)
constexpr int TY  = 8;            // output rows per block
constexpr int RCOLS = TXP + 4;    // 132 raw columns (with +-2 halo)
constexpr int PCOLS = 68;         // packed half2 columns: pc -> (col pc, col pc+64)

// exact fp32 boundary path
__device__ __forceinline__ float boundary_median(const float (*raw)[RCOLS],
                                                 int ty, int lc, int x, int y)
{
    const float FINF = __int_as_float(0x7f800000);
    float v[25];
    #pragma unroll
    for (int dy = -2; dy <= 2; dy++) {
        #pragma unroll
        for (int dx = -2; dx <= 2; dx++) {
            int yy = y + dy, xx = x + dx;
            bool ok = (yy >= 0) && (yy <= H - 2) && (xx >= 0) && (xx <= W - 2);
            float val = raw[ty + 2 + dy][lc + dx];
            v[(dy + 2) * 5 + (dx + 2)] = ok ? val : FINF;
        }
    }
    #pragma unroll
    for (int i = 0; i < 13; i++) {
        #pragma unroll
        for (int j = i + 1; j < 25; j++) {
            CEf(v[i], v[j]);
        }
    }
    int ylo = y - 2 < 0 ? 0 : y - 2;
    int yhi = y + 2 > H - 2 ? H - 2 : y + 2;
    int xlo = x - 2 < 0 ? 0 : x - 2;
    int xhi = x + 2 > W - 2 ? W - 2 : x + 2;
    int n  = (yhi - ylo + 1) * (xhi - xlo + 1);
    int li = (n - 1) >> 1, hi = n >> 1;
    float lo = v[0], hh = v[0];
    #pragma unroll
    for (int k = 0; k < 13; k++) {
        if (k == li) lo = v[k];
        if (k == hi) hh = v[k];
    }
    return 0.5f * (lo + hh);
}

// Doubly-sorted-matrix median-of-25 over sorted columns sc[base+0..4][0..4]
// (both packed halves independently).
__device__ __forceinline__ half2 median25_packed(const half2 (*sc)[5], int base)
{
    half2 a03, a04, a12, a13, a14, a21, a22, a23, a30, a31, a32, a40, a41;
    {   // row 0: ranks {3,4}
        half2 q0 = sc[base+0][0], q1 = sc[base+1][0], q2 = sc[base+2][0],
              q3 = sc[base+3][0], q4 = sc[base+4][0];
        CE2(q0,q1); CE2(q2,q3);
        half2 mx4 = MX2(q1,q3);
        half2 sec = MX2(MN2(q1,q3), MX2(q0,q2));
        a04 = MX2(mx4, q4);
        a03 = MX2(sec, MN2(mx4, q4));
    }
    {   // row 1: ranks {2,3,4}
        half2 q0 = sc[base+0][1], q1 = sc[base+1][1], q2 = sc[base+2][1],
              q3 = sc[base+3][1], q4 = sc[base+4][1];
        CE2(q0,q1); CE2(q2,q3);
        half2 x2p = MX2(q0,q2);
        half2 x1p = MN2(q1,q3), x3p = MX2(q1,q3);
        half2 s1 = MN2(x1p,x2p), s2 = MX2(x1p,x2p), s3 = x3p;
        a14 = MX2(s3, q4);
        a13 = MX2(s2, MN2(s3, q4));
        a12 = MN2(MX2(q4, s1), s2);
    }
    {   // row 2: ranks {1,2,3}
        half2 q0 = sc[base+0][2], q1 = sc[base+1][2], q2 = sc[base+2][2],
              q3 = sc[base+3][2], q4 = sc[base+4][2];
        CE2(q0,q1); CE2(q2,q3); CE2(q0,q2); CE2(q1,q3); CE2(q1,q2);  // sort4
        a21 = MN2(q1, MX2(q0, q4));
        a22 = MN2(MX2(q4, q1), q2);
        a23 = MX2(q2, MN2(q3, q4));
    }
    {   // row 3: ranks {0,1,2}
        half2 q0 = sc[base+0][3], q1 = sc[base+1][3], q2 = sc[base+2][3],
              q3 = sc[base+3][3], q4 = sc[base+4][3];
        CE2(q0,q1); CE2(q2,q3);
        half2 y1p = MN2(q1,q3);
        half2 s0 = MN2(q0,q2), y2p = MX2(q0,q2);
        half2 t1 = MN2(y2p,y1p), t2 = MX2(y2p,y1p);
        a30 = MN2(s0, q4);
        a31 = MN2(t1, MX2(s0, q4));
        a32 = MX2(MN2(q4, t2), t1);
    }
    {   // row 4: ranks {0,1}
        half2 q0 = sc[base+0][4], q1 = sc[base+1][4], q2 = sc[base+2][4],
              q3 = sc[base+3][4], q4 = sc[base+4][4];
        CE2(q0,q1); CE2(q2,q3);
        half2 mn4 = MN2(q0,q2);
        half2 sec = MN2(MX2(q0,q2), MN2(q1,q3));
        a40 = MN2(mn4, q4);
        a41 = MN2(sec, MX2(mn4, q4));
    }
    // Level 2: median of 13 candidates -> median of 7
    half2 u  = MN2(a21, a12), U  = MX2(a21, a12);
    half2 b04 = MX2(U, a04);
    half2 b03 = MX2(MN2(U, a04), MX2(u, a03));
    half2 w  = MN2(a32, a23), Wv = MX2(a32, a23);
    half2 b20 = MN2(a40, w);
    half2 b21 = MN2(MX2(a40, w), MN2(a41, Wv));
    half2 m0 = MN2(a30, a13), m3 = MX2(a31, a14);
    half2 tA = MX2(a30, a13), tB = MN2(a31, a14);
    half2 m1 = MN2(tA, tB), m2 = MX2(tA, tB);
    half2 b11 = MN2(m1, MX2(m0, a22));
    half2 b12 = MN2(MX2(a22, m1), m2);
    half2 b13 = MX2(m2, MN2(m3, a22));
    // Level 3: median of 7 via med3 of antidiagonal of padded 3x3
    half2 e0 = MX2(b11, b03);
    half2 e2 = MN2(b21, b13);
    half2 mnp = MN2(b20, b12);
    half2 e1 = MX2(mnp, MN2(MX2(b20, b12), b04));   // med3(b20,b12,b04)
    half2 mne = MN2(e0, e1);
    return MX2(mne, MN2(MX2(e0, e1), e2));          // med3(e0,e1,e2)
}

__global__ __launch_bounds__(256) void median5_kernel(const float* __restrict__ img,
                                                      float* __restrict__ out)
{
    __shared__ float raw [TY + 4][RCOLS];      // fp32 raw tile with halo (clamped)
    __shared__ half2 scol[TY][PCOLS][5];       // packed sorted 5-columns

    const int tid = threadIdx.x;               // 0..255
    const int x0  = blockIdx.x * TXP;
    const int y0  = blockIdx.y * TY;
    const int ch  = blockIdx.z;
    const float* src = img + (size_t)ch * H * W;

    // ---- Phase 0: load raw tile (clamped coords; masking happens later) ----
    for (int i = tid; i < (TY + 4) * RCOLS; i += 256) {
        int r = i / RCOLS, c = i % RCOLS;
        int gy = y0 - 2 + r; gy = gy < 0 ? 0 : (gy > H - 1 ? H - 1 : gy);
        int gx = x0 - 2 + c; gx = gx < 0 ? 0 : (gx > W - 1 ? W - 1 : gx);
        raw[r][c] = src[gy * W + gx];
    }
    __syncthreads();

    // ---- Phase A: packed sorted vertical 5-columns ----
    // packed column pc holds (global col x0-2+pc) in .lo and (x0+62+pc) in .hi
    for (int i = tid; i < TY * PCOLS; i += 256) {
        int yr = i / PCOLS, pc = i % PCOLS;
        half2 v0 = __floats2half2_rn(raw[yr + 0][pc], raw[yr + 0][pc + 64]);
        half2 v1 = __floats2half2_rn(raw[yr + 1][pc], raw[yr + 1][pc + 64]);
        half2 v2 = __floats2half2_rn(raw[yr + 2][pc], raw[yr + 2][pc + 64]);
        half2 v3 = __floats2half2_rn(raw[yr + 3][pc], raw[yr + 3][pc + 64]);
        half2 v4 = __floats2half2_rn(raw[yr + 4][pc], raw[yr + 4][pc + 64]);
        // optimal 9-CE sort5 (independently per half)
        CE2(v0,v1); CE2(v3,v4); CE2(v2,v4); CE2(v2,v3); CE2(v1,v4);
        CE2(v0,v3); CE2(v0,v2); CE2(v1,v3); CE2(v1,v2);
        scol[yr][pc][0] = v0; scol[yr][pc][1] = v1; scol[yr][pc][2] = v2;
        scol[yr][pc][3] = v3; scol[yr][pc][4] = v4;
    }
    __syncthreads();

    const int tx = tid & 31, ty = tid >> 5;
    const int y  = y0 + ty;

    // chain 0: pixels x0+tx,    x0+tx+64   (packed cols tx+0..tx+4)
    // chain 1: pixels x0+tx+32, x0+tx+96   (packed cols tx+32..tx+36)
    const int xa = x0 + tx;        // chain0 lo
    const int xb = xa + 64;        // chain0 hi
    const int xc = xa + 32;        // chain1 lo
    const int xd = xa + 96;        // chain1 hi

    const bool yint = ((unsigned)(y - 2) <= (unsigned)(H - 6));
    const bool i_a = yint && ((unsigned)(xa - 2) <= (unsigned)(W - 6));
    const bool i_b = yint && ((unsigned)(xb - 2) <= (unsigned)(W - 6));
    const bool i_c = yint && ((unsigned)(xc - 2) <= (unsigned)(W - 6));
    const bool i_d = yint && ((unsigned)(xd - 2) <= (unsigned)(W - 6));

    float* orow = out + (size_t)ch * H * W + (size_t)y * W;

    if (i_a && i_b && i_c && i_d) {
        const half2 (*sc)[5] = scol[ty];
        half2 med0 = median25_packed(sc, tx);        // independent chain A
        half2 med1 = median25_packed(sc, tx + 32);   // independent chain B
        orow[xa] = __low2float(med0);
        orow[xb] = __high2float(med0);
        orow[xc] = __low2float(med1);
        orow[xd] = __high2float(med1);
    } else {
        // ---- Boundary path: exact fp32 per pixel ----
        orow[xa] = boundary_median(raw, ty, tx + 2,   xa, y);
        orow[xb] = boundary_median(raw, ty, tx + 66,  xb, y);
        orow[xc] = boundary_median(raw, ty, tx + 34,  xc, y);
        orow[xd] = boundary_median(raw, ty, tx + 98,  xd, y);
    }
}

extern "C" void kernel_launch(void* const* d_in, const int* in_sizes, int n_in,
                              void* d_out, int out_size)
{
    (void)in_sizes; (void)n_in; (void)out_size;
    const float* img = (const float*)d_in[0];
    float* out = (float*)d_out;
    dim3 block(256, 1, 1);
    dim3 grid(W / TXP, H / TY, C);
    median5_kernel<<<grid, block>>>(img, out);
}

// round 13
// speedup vs baseline: 1.4526x; 1.4526x over previous
#include <cuda_runtime.h>
#include <cuda_fp16.h>

// 5x5 masked median filter, 3x1024x1024 fp32, f16x2-packed (2 pixels/lane),
// occupancy-forced to 8 blocks/SM (regs <= 32, 64 warps).
// Reference semantics: tap (y+dy, x+dx) valid iff 0<=y+dy<=H-2 && 0<=x+dx<=W-2.
// Output = mean of the two middle order statistics of valid taps.
// Interior: exact doubly-sorted-matrix selection in half2 (HMNMX2).
// Boundary (~1%): exact fp32 inf-masked partial selection sort.

#define MN2 __hmin2
#define MX2 __hmax2
#define CE2(a,b) { half2 _t2 = MN2(a,b); (b) = MX2(a,b); (a) = _t2; }
#define MNf fminf
#define MXf fmaxf
#define CEf(a,b) { float _tf = MNf(a,b); (b) = MXf(a,b); (a) = _tf; }

constexpr int H   = 1024;
constexpr int W   = 1024;
constexpr int C   = 3;
constexpr int TXP = 64;          // output pixels per block in x (32 lanes x 2)
constexpr int TY  = 8;           // output rows per block
constexpr int RCOLS = TXP + 4;   // 68 raw columns (with +-2 halo)
constexpr int PCOLS = 36;        // packed half2 columns: pc -> (col pc, col pc+32)

// exact fp32 boundary path
__device__ __forceinline__ float boundary_median(const float (*raw)[RCOLS],
                                                 int ty, int lc, int x, int y)
{
    const float FINF = __int_as_float(0x7f800000);
    float v[25];
    #pragma unroll
    for (int dy = -2; dy <= 2; dy++) {
        #pragma unroll
        for (int dx = -2; dx <= 2; dx++) {
            int yy = y + dy, xx = x + dx;
            bool ok = (yy >= 0) && (yy <= H - 2) && (xx >= 0) && (xx <= W - 2);
            float val = raw[ty + 2 + dy][lc + dx];
            v[(dy + 2) * 5 + (dx + 2)] = ok ? val : FINF;
        }
    }
    #pragma unroll
    for (int i = 0; i < 13; i++) {
        #pragma unroll
        for (int j = i + 1; j < 25; j++) {
            CEf(v[i], v[j]);
        }
    }
    int ylo = y - 2 < 0 ? 0 : y - 2;
    int yhi = y + 2 > H - 2 ? H - 2 : y + 2;
    int xlo = x - 2 < 0 ? 0 : x - 2;
    int xhi = x + 2 > W - 2 ? W - 2 : x + 2;
    int n  = (yhi - ylo + 1) * (xhi - xlo + 1);
    int li = (n - 1) >> 1, hi = n >> 1;
    float lo = v[0], hh = v[0];
    #pragma unroll
    for (int k = 0; k < 13; k++) {
        if (k == li) lo = v[k];
        if (k == hi) hh = v[k];
    }
    return 0.5f * (lo + hh);
}

__global__ __launch_bounds__(256, 8) void median5_kernel(const float* __restrict__ img,
                                                         float* __restrict__ out)
{
    __shared__ float raw [TY + 4][RCOLS];      // fp32 raw tile with halo (clamped)
    __shared__ half2 scol[TY][PCOLS][5];       // packed sorted 5-columns

    const int tid = threadIdx.x;               // 0..255
    const int x0  = blockIdx.x * TXP;
    const int y0  = blockIdx.y * TY;
    const int ch  = blockIdx.z;
    const float* src = img + (size_t)ch * H * W;

    // ---- Phase 0: load raw tile (clamped coords; masking happens later) ----
    for (int i = tid; i < (TY + 4) * RCOLS; i += 256) {
        int r = i / RCOLS, c = i % RCOLS;
        int gy = y0 - 2 + r; gy = gy < 0 ? 0 : (gy > H - 1 ? H - 1 : gy);
        int gx = x0 - 2 + c; gx = gx < 0 ? 0 : (gx > W - 1 ? W - 1 : gx);
        raw[r][c] = src[gy * W + gx];
    }
    __syncthreads();

    // ---- Phase A: packed sorted vertical 5-columns ----
    // packed column pc holds (global col x0-2+pc) in .lo and (x0+30+pc) in .hi
    for (int i = tid; i < TY * PCOLS; i += 256) {
        int yr = i / PCOLS, pc = i % PCOLS;
        half2 v0 = __floats2half2_rn(raw[yr + 0][pc], raw[yr + 0][pc + 32]);
        half2 v1 = __floats2half2_rn(raw[yr + 1][pc], raw[yr + 1][pc + 32]);
        half2 v2 = __floats2half2_rn(raw[yr + 2][pc], raw[yr + 2][pc + 32]);
        half2 v3 = __floats2half2_rn(raw[yr + 3][pc], raw[yr + 3][pc + 32]);
        half2 v4 = __floats2half2_rn(raw[yr + 4][pc], raw[yr + 4][pc + 32]);
        // optimal 9-CE sort5 (independently per half)
        CE2(v0,v1); CE2(v3,v4); CE2(v2,v4); CE2(v2,v3); CE2(v1,v4);
        CE2(v0,v3); CE2(v0,v2); CE2(v1,v3); CE2(v1,v2);
        scol[yr][pc][0] = v0; scol[yr][pc][1] = v1; scol[yr][pc][2] = v2;
        scol[yr][pc][3] = v3; scol[yr][pc][4] = v4;
    }
    __syncthreads();

    const int tx = tid & 31, ty = tid >> 5;
    const int x  = x0 + tx;          // lo pixel
    const int xh = x + 32;           // hi pixel
    const int y  = y0 + ty;

    const bool yint   = ((unsigned)(y  - 2) <= (unsigned)(H - 6));
    const bool int_lo = yint && ((unsigned)(x  - 2) <= (unsigned)(W - 6));
    const bool int_hi = yint && ((unsigned)(xh - 2) <= (unsigned)(W - 6));

    float* orow = out + (size_t)ch * H * W + (size_t)y * W;

    if (int_lo && int_hi) {
        const half2 (*sc)[5] = &scol[ty][tx];
        // ---- Packed doubly-sorted-matrix median selection (both halves) ----
        half2 a03, a04, a12, a13, a14, a21, a22, a23, a30, a31, a32, a40, a41;
        {   // row 0: ranks {3,4}
            half2 q0 = sc[0][0], q1 = sc[1][0], q2 = sc[2][0],
                  q3 = sc[3][0], q4 = sc[4][0];
            CE2(q0,q1); CE2(q2,q3);
            half2 mx4 = MX2(q1,q3);
            half2 sec = MX2(MN2(q1,q3), MX2(q0,q2));
            a04 = MX2(mx4, q4);
            a03 = MX2(sec, MN2(mx4, q4));
        }
        {   // row 1: ranks {2,3,4}
            half2 q0 = sc[0][1], q1 = sc[1][1], q2 = sc[2][1],
                  q3 = sc[3][1], q4 = sc[4][1];
            CE2(q0,q1); CE2(q2,q3);
            half2 x2p = MX2(q0,q2);
            half2 x1p = MN2(q1,q3), x3p = MX2(q1,q3);
            half2 s1 = MN2(x1p,x2p), s2 = MX2(x1p,x2p), s3 = x3p;
            a14 = MX2(s3, q4);
            a13 = MX2(s2, MN2(s3, q4));
            a12 = MN2(MX2(q4, s1), s2);
        }
        {   // row 2: ranks {1,2,3}
            half2 q0 = sc[0][2], q1 = sc[1][2], q2 = sc[2][2],
                  q3 = sc[3][2], q4 = sc[4][2];
            CE2(q0,q1); CE2(q2,q3); CE2(q0,q2); CE2(q1,q3); CE2(q1,q2);  // sort4
            a21 = MN2(q1, MX2(q0, q4));
            a22 = MN2(MX2(q4, q1), q2);
            a23 = MX2(q2, MN2(q3, q4));
        }
        {   // row 3: ranks {0,1,2}
            half2 q0 = sc[0][3], q1 = sc[1][3], q2 = sc[2][3],
                  q3 = sc[3][3], q4 = sc[4][3];
            CE2(q0,q1); CE2(q2,q3);
            half2 y1p = MN2(q1,q3);
            half2 s0 = MN2(q0,q2), y2p = MX2(q0,q2);
            half2 t1 = MN2(y2p,y1p), t2 = MX2(y2p,y1p);
            a30 = MN2(s0, q4);
            a31 = MN2(t1, MX2(s0, q4));
            a32 = MX2(MN2(q4, t2), t1);
        }
        {   // row 4: ranks {0,1}
            half2 q0 = sc[0][4], q1 = sc[1][4], q2 = sc[2][4],
                  q3 = sc[3][4], q4 = sc[4][4];
            CE2(q0,q1); CE2(q2,q3);
            half2 mn4 = MN2(q0,q2);
            half2 sec = MN2(MX2(q0,q2), MN2(q1,q3));
            a40 = MN2(mn4, q4);
            a41 = MN2(sec, MX2(mn4, q4));
        }
        // Level 2: median of 13 candidates -> median of 7
        half2 u  = MN2(a21, a12), U  = MX2(a21, a12);
        half2 b04 = MX2(U, a04);
        half2 b03 = MX2(MN2(U, a04), MX2(u, a03));
        half2 w  = MN2(a32, a23), Wv = MX2(a32, a23);
        half2 b20 = MN2(a40, w);
        half2 b21 = MN2(MX2(a40, w), MN2(a41, Wv));
        half2 m0 = MN2(a30, a13), m3 = MX2(a31, a14);
        half2 tA = MX2(a30, a13), tB = MN2(a31, a14);
        half2 m1 = MN2(tA, tB), m2 = MX2(tA, tB);
        half2 b11 = MN2(m1, MX2(m0, a22));
        half2 b12 = MN2(MX2(a22, m1), m2);
        half2 b13 = MX2(m2, MN2(m3, a22));
        // Level 3: median of 7 via med3 of antidiagonal of padded 3x3
        half2 e0 = MX2(b11, b03);
        half2 e2 = MN2(b21, b13);
        half2 mnp = MN2(b20, b12);
        half2 e1 = MX2(mnp, MN2(MX2(b20, b12), b04));   // med3(b20,b12,b04)
        half2 mne = MN2(e0, e1);
        half2 med = MX2(mne, MN2(MX2(e0, e1), e2));     // med3(e0,e1,e2)

        orow[x]  = __low2float(med);
        orow[xh] = __high2float(med);
    } else {
        // ---- Boundary path: exact fp32 per pixel ----
        orow[x]  = boundary_median(raw, ty, tx + 2,  x,  y);
        orow[xh] = boundary_median(raw, ty, tx + 34, xh, y);
    }
}

extern "C" void kernel_launch(void* const* d_in, const int* in_sizes, int n_in,
                              void* d_out, int out_size)
{
    (void)in_sizes; (void)n_in; (void)out_size;
    const float* img = (const float*)d_in[0];
    float* out = (float*)d_out;
    dim3 block(256, 1, 1);
    dim3 grid(W / TXP, H / TY, C);
    median5_kernel<<<grid, block>>>(img, out);
}

// round 17
// speedup vs baseline: 2.5986x; 1.7889x over previous
#include <cuda_runtime.h>
#include <cuda_fp16.h>

// 5x5 masked median filter, 3x1024x1024 fp32.
// Kernel 1 (hot): f16x2-packed doubly-sorted-matrix median, 2 px/lane,
//                 branch-free (computes garbage on the 5-px-wide borders).
// Kernel 2 (tiny): exact fp32 masked median for the 10215 border px/channel,
//                  overwrites kernel 1's garbage there.
// Reference semantics: tap (y+dy,x+dx) valid iff 0<=y+dy<=H-2 && 0<=x+dx<=W-2.
// Output = mean of the two middle order statistics of valid taps.

#define MN2 __hmin2
#define MX2 __hmax2
#define CE2(a,b) { half2 _t2 = MN2(a,b); (b) = MX2(a,b); (a) = _t2; }
#define MNf fminf
#define MXf fmaxf
#define CEf(a,b) { float _tf = MNf(a,b); (b) = MXf(a,b); (a) = _tf; }

constexpr int H   = 1024;
constexpr int W   = 1024;
constexpr int C   = 3;
constexpr int TXP = 64;          // output pixels per block in x (32 lanes x 2)
constexpr int TY  = 8;           // output rows per block
constexpr int PCOLS = 36;        // packed half2 cols: pc -> (col x0-2+pc, col x0+30+pc)

// ---------------------------------------------------------------- hot kernel
__global__ __launch_bounds__(256, 8) void median5_kernel(const float* __restrict__ img,
                                                         float* __restrict__ out)
{
    __shared__ half2 rawp[TY + 4][PCOLS];      // packed raw tile with +-2 y-halo
    __shared__ half2 scol[TY][PCOLS][5];       // packed sorted 5-columns

    const int tid = threadIdx.x;               // 0..255
    const int x0  = blockIdx.x * TXP;
    const int y0  = blockIdx.y * TY;
    const int ch  = blockIdx.z;
    const float* src = img + (size_t)ch * H * W;

    // ---- Phase 0: load + convert + pack raw tile (x/y clamped) ----
    for (int i = tid; i < (TY + 4) * PCOLS; i += 256) {
        int r = i / PCOLS, pc = i % PCOLS;
        int gy = y0 - 2 + r; gy = gy < 0 ? 0 : (gy > H - 1 ? H - 1 : gy);
        int xl = x0 + pc - 2;  xl = xl < 0 ? 0 : (xl > W - 1 ? W - 1 : xl);
        int xh = x0 + pc + 30; xh = xh > W - 1 ? W - 1 : xh;
        const float* row = src + (size_t)gy * W;
        rawp[r][pc] = __floats2half2_rn(row[xl], row[xh]);
    }
    __syncthreads();

    // ---- Phase A: packed sorted vertical 5-columns ----
    for (int i = tid; i < TY * PCOLS; i += 256) {
        int yr = i / PCOLS, pc = i % PCOLS;
        half2 v0 = rawp[yr + 0][pc];
        half2 v1 = rawp[yr + 1][pc];
        half2 v2 = rawp[yr + 2][pc];
        half2 v3 = rawp[yr + 3][pc];
        half2 v4 = rawp[yr + 4][pc];
        // optimal 9-CE sort5 (independently per half)
        CE2(v0,v1); CE2(v3,v4); CE2(v2,v4); CE2(v2,v3); CE2(v1,v4);
        CE2(v0,v3); CE2(v0,v2); CE2(v1,v3); CE2(v1,v2);
        scol[yr][pc][0] = v0; scol[yr][pc][1] = v1; scol[yr][pc][2] = v2;
        scol[yr][pc][3] = v3; scol[yr][pc][4] = v4;
    }
    __syncthreads();

    const int tx = tid & 31, ty = tid >> 5;
    const int x  = x0 + tx;          // lo pixel
    const int y  = y0 + ty;
    const half2 (*sc)[5] = &scol[ty][tx];

    // ---- Packed doubly-sorted-matrix median selection (branch-free) ----
    half2 a03, a04, a12, a13, a14, a21, a22, a23, a30, a31, a32, a40, a41;
    {   // row 0: ranks {3,4}
        half2 q0 = sc[0][0], q1 = sc[1][0], q2 = sc[2][0],
              q3 = sc[3][0], q4 = sc[4][0];
        CE2(q0,q1); CE2(q2,q3);
        half2 mx4 = MX2(q1,q3);
        half2 sec = MX2(MN2(q1,q3), MX2(q0,q2));
        a04 = MX2(mx4, q4);
        a03 = MX2(sec, MN2(mx4, q4));
    }
    {   // row 1: ranks {2,3,4}
        half2 q0 = sc[0][1], q1 = sc[1][1], q2 = sc[2][1],
              q3 = sc[3][1], q4 = sc[4][1];
        CE2(q0,q1); CE2(q2,q3);
        half2 x2p = MX2(q0,q2);
        half2 x1p = MN2(q1,q3), x3p = MX2(q1,q3);
        half2 s1 = MN2(x1p,x2p), s2 = MX2(x1p,x2p), s3 = x3p;
        a14 = MX2(s3, q4);
        a13 = MX2(s2, MN2(s3, q4));
        a12 = MN2(MX2(q4, s1), s2);
    }
    {   // row 2: ranks {1,2,3}
        half2 q0 = sc[0][2], q1 = sc[1][2], q2 = sc[2][2],
              q3 = sc[3][2], q4 = sc[4][2];
        CE2(q0,q1); CE2(q2,q3); CE2(q0,q2); CE2(q1,q3); CE2(q1,q2);  // sort4
        a21 = MN2(q1, MX2(q0, q4));
        a22 = MN2(MX2(q4, q1), q2);
        a23 = MX2(q2, MN2(q3, q4));
    }
    {   // row 3: ranks {0,1,2}
        half2 q0 = sc[0][3], q1 = sc[1][3], q2 = sc[2][3],
              q3 = sc[3][3], q4 = sc[4][3];
        CE2(q0,q1); CE2(q2,q3);
        half2 y1p = MN2(q1,q3);
        half2 s0 = MN2(q0,q2), y2p = MX2(q0,q2);
        half2 t1 = MN2(y2p,y1p), t2 = MX2(y2p,y1p);
        a30 = MN2(s0, q4);
        a31 = MN2(t1, MX2(s0, q4));
        a32 = MX2(MN2(q4, t2), t1);
    }
    {   // row 4: ranks {0,1}
        half2 q0 = sc[0][4], q1 = sc[1][4], q2 = sc[2][4],
              q3 = sc[3][4], q4 = sc[4][4];
        CE2(q0,q1); CE2(q2,q3);
        half2 mn4 = MN2(q0,q2);
        half2 sec = MN2(MX2(q0,q2), MN2(q1,q3));
        a40 = MN2(mn4, q4);
        a41 = MN2(sec, MX2(mn4, q4));
    }
    // Level 2: median of 13 candidates -> median of 7
    half2 u  = MN2(a21, a12), U  = MX2(a21, a12);
    half2 b04 = MX2(U, a04);
    half2 b03 = MX2(MN2(U, a04), MX2(u, a03));
    half2 w  = MN2(a32, a23), Wv = MX2(a32, a23);
    half2 b20 = MN2(a40, w);
    half2 b21 = MN2(MX2(a40, w), MN2(a41, Wv));
    half2 m0 = MN2(a30, a13), m3 = MX2(a31, a14);
    half2 tA = MX2(a30, a13), tB = MN2(a31, a14);
    half2 m1 = MN2(tA, tB), m2 = MX2(tA, tB);
    half2 b11 = MN2(m1, MX2(m0, a22));
    half2 b12 = MN2(MX2(a22, m1), m2);
    half2 b13 = MX2(m2, MN2(m3, a22));
    // Level 3: median of 7 via med3 of antidiagonal of padded 3x3
    half2 e0 = MX2(b11, b03);
    half2 e2 = MN2(b21, b13);
    half2 mnp = MN2(b20, b12);
    half2 e1 = MX2(mnp, MN2(MX2(b20, b12), b04));   // med3(b20,b12,b04)
    half2 mne = MN2(e0, e1);
    half2 med = MX2(mne, MN2(MX2(e0, e1), e2));     // med3(e0,e1,e2)

    float* orow = out + (size_t)ch * H * W + (size_t)y * W;
    orow[x]      = __low2float(med);
    orow[x + 32] = __high2float(med);
}

// ------------------------------------------------------------ boundary kernel
// Exact fp32 masked median for all pixels with x<2 || x>1020 || y<2 || y>1020.
constexpr int NB = 5 * W + (H - 5) * 5;   // 5120 + 5095 = 10215 per channel

__global__ __launch_bounds__(256) void boundary_kernel(const float* __restrict__ img,
                                                       float* __restrict__ out)
{
    int idx = blockIdx.x * 256 + threadIdx.x;
    int ch  = blockIdx.y;
    if (idx >= NB) return;

    int x, y;
    if (idx < 5 * W) {                 // 5 full rows: y in {0,1,1021,1022,1023}
        int r = idx >> 10;             // W = 1024
        x = idx & (W - 1);
        y = (r < 2) ? r : (H - 5 + r); // r=2,3,4 -> 1021,1022,1023
    } else {                           // 5 cols x 1019 middle rows
        int j = idx - 5 * W;
        int row = j / 5, c = j - row * 5;
        y = 2 + row;
        x = (c < 2) ? c : (W - 5 + c); // c=2,3,4 -> 1021,1022,1023
    }

    const float* src = img + (size_t)ch * H * W;
    const float FINF = __int_as_float(0x7f800000);
    float v[25];
    #pragma unroll
    for (int dy = -2; dy <= 2; dy++) {
        #pragma unroll
        for (int dx = -2; dx <= 2; dx++) {
            int yy = y + dy, xx = x + dx;
            bool ok = (yy >= 0) && (yy <= H - 2) && (xx >= 0) && (xx <= W - 2);
            int yc = yy < 0 ? 0 : (yy > H - 1 ? H - 1 : yy);
            int xc = xx < 0 ? 0 : (xx > W - 1 ? W - 1 : xx);
            float val = src[(size_t)yc * W + xc];
            v[(dy + 2) * 5 + (dx + 2)] = ok ? val : FINF;
        }
    }
    #pragma unroll
    for (int i = 0; i < 13; i++) {
        #pragma unroll
        for (int j = i + 1; j < 25; j++) {
            CEf(v[i], v[j]);
        }
    }
    int ylo = y - 2 < 0 ? 0 : y - 2;
    int yhi = y + 2 > H - 2 ? H - 2 : y + 2;
    int xlo = x - 2 < 0 ? 0 : x - 2;
    int xhi = x + 2 > W - 2 ? W - 2 : x + 2;
    int n  = (yhi - ylo + 1) * (xhi - xlo + 1);
    int li = (n - 1) >> 1, hi = n >> 1;
    float lo = v[0], hh = v[0];
    #pragma unroll
    for (int k = 0; k < 13; k++) {
        if (k == li) lo = v[k];
        if (k == hi) hh = v[k];
    }
    out[(size_t)ch * H * W + (size_t)y * W + x] = 0.5f * (lo + hh);
}

extern "C" void kernel_launch(void* const* d_in, const int* in_sizes, int n_in,
                              void* d_out, int out_size)
{
    (void)in_sizes; (void)n_in; (void)out_size;
    const float* img = (const float*)d_in[0];
    float* out = (float*)d_out;

    dim3 block(256, 1, 1);
    dim3 grid(W / TXP, H / TY, C);
    median5_kernel<<<grid, block>>>(img, out);

    dim3 bgrid((NB + 255) / 256, C, 1);
    boundary_kernel<<<bgrid, block>>>(img, out);
}